// round 14
// baseline (speedup 1.0000x reference)
#include <cuda_runtime.h>
#include <stdint.h>

// Problem constants
#define NB       64
#define NH       512
#define NW       512
#define NC       3
#define NUM_MASK 3072          // masked patches per image

// ---------------------------------------------------------------------------
// Champion R4 body, grid TRANSPOSED (x=image, y=patch-row).
// Per-block work is byte-identical to the 47.6us champion; only the CTA->
// address interleaving changes: wave-1's 592 co-resident blocks now stream
// the same patch-row band across all 64 images (3 MB strides spanning the
// full 192 MB) instead of consecutive bands of ~9 images. Tests whether
// spreading concurrent streams over more DRAM pages/channels lifts the
// ~67% DRAM-active plateau. Pure scheduling permutation -> bounded risk.
//
// Prologue: build this block's 64-patch keep bitmap directly from
// mask_indices (8 coalesced L2-hit index loads/thread, range-test,
// atomicOr into 2 shared words).
//
// Main: a patch spans 8 consecutive rows sharing one mask bit. Each thread
// owns one float4 column across the 8 rows of its patch band:
//   - keep: 8x LDG.128 (front-batched -> MLP=8) + 8x STG.128
//   - drop: 8x STG.128 of zeros, image never read (saves 75% read traffic)
// Row stride = 384 float4 = 6144 B; fully coalesced.
__global__ void __launch_bounds__(384)
random_mask_kernel(const float4* __restrict__ img,
                   const int*    __restrict__ mask_indices,
                   float4*       __restrict__ out) {
    const int b  = blockIdx.x;            // image       [0, 64)
    const int pr = blockIdx.y;            // patch row   [0, 64)
    const int t  = threadIdx.x;           // float4 col  [0, 384)

    // ---- build 64-bit masked-bitmap for this (image, patch-row) ----
    __shared__ uint32_t masked_bits[2];
    if (t < 2) masked_bits[t] = 0;
    __syncthreads();

    const int* mi = mask_indices + b * NUM_MASK;
    const int lo = pr << 6;               // first patch id of this row
#pragma unroll
    for (int j = 0; j < 8; j++) {
        int idx = mi[t + j * 384];        // coalesced, L2-resident
        unsigned d = (unsigned)(idx - lo);
        if (d < 64u) atomicOr(&masked_bits[d >> 5], 1u << (d & 31));
    }
    __syncthreads();

    const int p = t / 6;                  // patch col: 6 float4 per patch
    const bool keep = !((masked_bits[p >> 5] >> (p & 31)) & 1u);

    // ---- stream the 8-row band ----
    const long base = ((long)(b * NH + (pr << 3)) * 384) + t;
    const float4* ip = img + base;
    float4*       op = out + base;

    if (keep) {
        float4 v[8];
#pragma unroll
        for (int r = 0; r < 8; r++) v[r] = __ldcs(ip + r * 384);
#pragma unroll
        for (int r = 0; r < 8; r++) __stcs(op + r * 384, v[r]);
    } else {
        const float4 z = make_float4(0.f, 0.f, 0.f, 0.f);
#pragma unroll
        for (int r = 0; r < 8; r++) __stcs(op + r * 384, z);
    }
}

// ---------------------------------------------------------------------------
extern "C" void kernel_launch(void* const* d_in, const int* in_sizes, int n_in,
                              void* d_out, int out_size) {
    const float4* img = (const float4*)d_in[0];       // images [64,512,512,3] f32
    const int* mask_indices = (const int*)d_in[1];    // [64, 3072] i32
    float4* out = (float4*)d_out;

    dim3 grid(NB, 64);                    // (images, patch-rows) — transposed
    random_mask_kernel<<<grid, 384>>>(img, mask_indices, out);
}

// round 15
// speedup vs baseline: 1.1657x; 1.1657x over previous
#include <cuda_runtime.h>
#include <stdint.h>

// Problem constants
#define NB       64
#define NH       512
#define NW       512
#define NC       3
#define NUM_MASK 3072          // masked patches per image

// ---------------------------------------------------------------------------
// FINAL kernel — converged optimum, best measured total 47.616 us
// (reproduced twice; kernel ~43.4-44.1 us, DRAM ~67-69% @ ~5.8 TB/s
// effective on the minimal 252 MB of traffic).
//
// Grid (NPH=64 patch-rows, NB=64 images); block = 384 threads.
// NOTE: grid order (x=patch-row, y=image) is load-bearing: co-resident
// blocks then cover consecutive bands of few images -> clustered DRAM
// streams + the per-image 12 KB index slice is reused by 64 consecutive
// blocks from L2. The transposed order measured 54.2 us (DRAM 54.7%).
//
// Prologue: build this block's 64-patch keep bitmap directly from
// mask_indices (no intermediate global mask, no builder kernel):
//   - each thread reads 8 indices of this image's 3072 (coalesced,
//     L2-resident)
//   - range-test against this patch-row, atomicOr into 2 shared words.
//
// Main: a patch spans 8 consecutive rows sharing one mask bit. Each thread
// owns one float4 column across the 8 rows of its patch band:
//   - keep: 8x LDG.128 (front-batched -> MLP=8) + 8x STG.128
//   - drop: 8x STG.128 of zeros, image never read (saves 75% read traffic)
// Consecutive threads touch consecutive float4s within a row -> fully
// coalesced. Row stride = 384 float4 = 6144 B.
//
// Tuning history (single-axis probes off this base, ALL regressed/tied):
//   R5 occupancy up (chunked loads, regs 30)      -> 44.9 us, DRAM 66%
//   R6 2 bands sequential per thread              -> 45.0 us, DRAM 66%
//   R7 MLP 16 (2 cols/thread, 192 thr)            -> 44.5 us, DRAM 66%
//   R8 default store policy (no .cs)              -> 43.6 us (tie)
//   R9 persistent 592 blocks                      -> 49.6 us, DRAM 60%
//   R10 256-bit v8.f32 ops                        -> 45.3 us, DRAM 64%
//   R12 2 bands concurrent (768 thr)              -> 45.6 us, DRAM 65%
//   R14 transposed grid order                     -> 54.2 us, DRAM 55%
// Remaining gap to HBM spec is read/write turnaround on an 80%-write
// stream; no SM-side lever moved it.
__global__ void __launch_bounds__(384)
random_mask_kernel(const float4* __restrict__ img,
                   const int*    __restrict__ mask_indices,
                   float4*       __restrict__ out) {
    const int pr = blockIdx.x;            // patch row   [0, 64)
    const int b  = blockIdx.y;            // image       [0, 64)
    const int t  = threadIdx.x;           // float4 col  [0, 384)

    // ---- build 64-bit masked-bitmap for this (image, patch-row) ----
    __shared__ uint32_t masked_bits[2];
    if (t < 2) masked_bits[t] = 0;
    __syncthreads();

    const int* mi = mask_indices + b * NUM_MASK;
    const int lo = pr << 6;               // first patch id of this row
#pragma unroll
    for (int j = 0; j < 8; j++) {
        int idx = mi[t + j * 384];        // coalesced, L2-resident
        unsigned d = (unsigned)(idx - lo);
        if (d < 64u) atomicOr(&masked_bits[d >> 5], 1u << (d & 31));
    }
    __syncthreads();

    const int p = t / 6;                  // patch col: 6 float4 per patch
    const bool keep = !((masked_bits[p >> 5] >> (p & 31)) & 1u);

    // ---- stream the 8-row band ----
    const long base = ((long)(b * NH + (pr << 3)) * 384) + t;
    const float4* ip = img + base;
    float4*       op = out + base;

    if (keep) {
        float4 v[8];
#pragma unroll
        for (int r = 0; r < 8; r++) v[r] = __ldcs(ip + r * 384);
#pragma unroll
        for (int r = 0; r < 8; r++) __stcs(op + r * 384, v[r]);
    } else {
        const float4 z = make_float4(0.f, 0.f, 0.f, 0.f);
#pragma unroll
        for (int r = 0; r < 8; r++) __stcs(op + r * 384, z);
    }
}

// ---------------------------------------------------------------------------
extern "C" void kernel_launch(void* const* d_in, const int* in_sizes, int n_in,
                              void* d_out, int out_size) {
    const float4* img = (const float4*)d_in[0];       // images [64,512,512,3] f32
    const int* mask_indices = (const int*)d_in[1];    // [64, 3072] i32
    float4* out = (float4*)d_out;

    dim3 grid(64, NB);                    // (patch-rows, images)
    random_mask_kernel<<<grid, 384>>>(img, mask_indices, out);
}

// round 16
// speedup vs baseline: 1.1727x; 1.0060x over previous
#include <cuda_runtime.h>
#include <stdint.h>

// Problem constants
#define NB       64
#define NH       512
#define NW       512
#define NC       3
#define NUM_MASK 3072          // masked patches per image

// ---------------------------------------------------------------------------
// Champion configuration with ONE isolated change: convergent store path.
// Previously divergent warps (mixed keep bits across the 5.33 patches a
// warp spans) issued 16 STG.128 under complementary masks + BSSY/BSYNC;
// now: v[] zero-init, predicated loads, single unconditional store loop ->
// 8 full-warp STG.128 always. Everything else byte-identical to the
// 47.6us champion (384 thr, x=patch-row/y=image grid, MLP=8, .cs).
//
// Prologue: build this block's 64-patch keep bitmap directly from
// mask_indices (8 coalesced L2-hit index loads/thread, range-test,
// atomicOr into 2 shared words).
//
// Main: a patch spans 8 consecutive rows sharing one mask bit. Each thread
// owns one float4 column across the 8 rows of its patch band:
//   - keep: 8x LDG.128 (front-batched -> MLP=8)
//   - drop: image never read (saves 75% read traffic)
//   - all:  8x STG.128, convergent
// Row stride = 384 float4 = 6144 B; fully coalesced.
__global__ void __launch_bounds__(384)
random_mask_kernel(const float4* __restrict__ img,
                   const int*    __restrict__ mask_indices,
                   float4*       __restrict__ out) {
    const int pr = blockIdx.x;            // patch row   [0, 64)
    const int b  = blockIdx.y;            // image       [0, 64)
    const int t  = threadIdx.x;           // float4 col  [0, 384)

    // ---- build 64-bit masked-bitmap for this (image, patch-row) ----
    __shared__ uint32_t masked_bits[2];
    if (t < 2) masked_bits[t] = 0;
    __syncthreads();

    const int* mi = mask_indices + b * NUM_MASK;
    const int lo = pr << 6;               // first patch id of this row
#pragma unroll
    for (int j = 0; j < 8; j++) {
        int idx = mi[t + j * 384];        // coalesced, L2-resident
        unsigned d = (unsigned)(idx - lo);
        if (d < 64u) atomicOr(&masked_bits[d >> 5], 1u << (d & 31));
    }
    __syncthreads();

    const int p = t / 6;                  // patch col: 6 float4 per patch
    const bool keep = !((masked_bits[p >> 5] >> (p & 31)) & 1u);

    // ---- stream the 8-row band ----
    const long base = ((long)(b * NH + (pr << 3)) * 384) + t;
    const float4* ip = img + base;
    float4*       op = out + base;

    float4 v[8];
#pragma unroll
    for (int r = 0; r < 8; r++) v[r] = make_float4(0.f, 0.f, 0.f, 0.f);

    if (keep) {
#pragma unroll
        for (int r = 0; r < 8; r++) v[r] = __ldcs(ip + r * 384);
    }

#pragma unroll
    for (int r = 0; r < 8; r++) __stcs(op + r * 384, v[r]);
}

// ---------------------------------------------------------------------------
extern "C" void kernel_launch(void* const* d_in, const int* in_sizes, int n_in,
                              void* d_out, int out_size) {
    const float4* img = (const float4*)d_in[0];       // images [64,512,512,3] f32
    const int* mask_indices = (const int*)d_in[1];    // [64, 3072] i32
    float4* out = (float4*)d_out;

    dim3 grid(64, NB);                    // (patch-rows, images)
    random_mask_kernel<<<grid, 384>>>(img, mask_indices, out);
}